// round 16
// baseline (speedup 1.0000x reference)
#include <cuda_runtime.h>
#include <math.h>
#include <stdint.h>

// Problem dims
#define SB 8
#define SS 2048
#define SD 1024
#define SG 4096          // 4*D
#define SQD 1024
#define SKD 256
#define SOH 64
#define MTOT (SB*SS)     // 16384

typedef unsigned long long ull;

// ---------------- scratch (static device globals; no allocation) -------------
__device__ float g_gxq[(size_t)MTOT * SG];
__device__ float g_gxk[(size_t)MTOT * SG];
__device__ float g_hqs[(size_t)MTOT * SD];
__device__ float g_hks[(size_t)MTOT * SD];
__device__ float g_t1q[(size_t)MTOT * SOH];
__device__ float g_t1k[(size_t)MTOT * SOH];
__device__ float g_xr[(size_t)MTOT * SD];    // tf32-rounded x
__device__ float g_wq[(size_t)SG * SD];      // tf32-rounded Wi_q
__device__ float g_wk[(size_t)SG * SD];      // tf32-rounded Wi_k
__device__ float g_h[2][2][SB * SD];

// per-LSTM barrier, each field on its own 128B line
struct __align__(128) Bar { volatile int count; int p0[31]; volatile int sense; int p1[31]; };
__device__ Bar g_bar[2];

// ---------------- helpers -----------------------------------------------------
__device__ __forceinline__ uint32_t f2tf32(float x)
{
    uint32_t u;
    asm("cvt.rna.tf32.f32 %0, %1;" : "=r"(u) : "f"(x));
    return u;
}

__device__ __forceinline__ void mma_tf32(float* d, const uint32_t* a, const uint32_t* b)
{
    asm volatile(
        "mma.sync.aligned.m16n8k8.row.col.f32.tf32.tf32.f32 "
        "{%0,%1,%2,%3}, {%4,%5,%6,%7}, {%8,%9}, {%0,%1,%2,%3};"
        : "+f"(d[0]), "+f"(d[1]), "+f"(d[2]), "+f"(d[3])
        : "r"(a[0]), "r"(a[1]), "r"(a[2]), "r"(a[3]), "r"(b[0]), "r"(b[1]));
}

__device__ __forceinline__ void ffma2(ull& d, ull a, ull b)
{
    asm("fma.rn.f32x2 %0, %1, %2, %0;" : "+l"(d) : "l"(a), "l"(b));
}

__device__ __forceinline__ float lo32f(ull v) { return __uint_as_float((unsigned)v); }
__device__ __forceinline__ float hi32f(ull v) { return __uint_as_float((unsigned)(v >> 32)); }

__device__ __forceinline__ uint32_t smem_u32(const void* p)
{
    return (uint32_t)__cvta_generic_to_shared(p);
}

#define CP_ASYNC16(dst, src) \
    asm volatile("cp.async.cg.shared.global [%0], [%1], 16;" :: "r"(dst), "l"(src))
#define CP_COMMIT() asm volatile("cp.async.commit_group;")
#define CP_WAIT1()  asm volatile("cp.async.wait_group 1;")
#define CP_WAIT0()  asm volatile("cp.async.wait_group 0;")

// ---------------- fused elementwise tf32 rounding (x, Wi_q, Wi_k) ------------
#define N4X (MTOT * SD / 4)
#define N4W (SG * SD / 4)

__global__ void round_all_k(const float4* __restrict__ x, float4* __restrict__ xr,
                            const float4* __restrict__ wqi, float4* __restrict__ wqo,
                            const float4* __restrict__ wki, float4* __restrict__ wko)
{
    int i = blockIdx.x * blockDim.x + threadIdx.x;
    const float4* in;
    float4* out;
    int idx;
    if (i < N4X)                { in = x;   out = xr;  idx = i; }
    else if (i < N4X + N4W)     { in = wqi; out = wqo; idx = i - N4X; }
    else if (i < N4X + 2 * N4W) { in = wki; out = wko; idx = i - N4X - N4W; }
    else return;
    float4 v = in[idx];
    v.x = __uint_as_float(f2tf32(v.x));
    v.y = __uint_as_float(f2tf32(v.y));
    v.z = __uint_as_float(f2tf32(v.z));
    v.w = __uint_as_float(f2tf32(v.w));
    out[idx] = v;
}

// ---------------- pipelined tf32 GEMM core -----------------------------------
#define STAGES 3
#define GBK 32
#define STR 36

template<int CVT>
__device__ __forceinline__ void gemm_body(
    const float* __restrict__ A, const float* __restrict__ Bm,
    const float* __restrict__ bias, float* __restrict__ C,
    int M, int N, int K, int relu,
    uint32_t (*As)[128 * STR], uint32_t (*Bs)[128 * STR])
{
    int tid = threadIdx.x, wid = tid >> 5, lane = tid & 31;
    int wm = wid & 1, wn = wid >> 1;
    int bm = blockIdx.y * 128, bn = blockIdx.x * 128;
    int gid = lane >> 2, tig = lane & 3;

    int r0 = tid >> 3;
    int c4 = (tid & 7) * 4;

    float acc[4][4][4];
    #pragma unroll
    for (int mt = 0; mt < 4; mt++)
        #pragma unroll
        for (int nt = 0; nt < 4; nt++)
            #pragma unroll
            for (int i = 0; i < 4; i++) acc[mt][nt][i] = 0.f;

    int nk = K / GBK;

    auto issue = [&](int s, int kt) {
        int kof = kt * GBK;
        #pragma unroll
        for (int j = 0; j < 4; j++) {
            int row = r0 + 32 * j;
            uint32_t da = smem_u32(&As[s][row * STR + c4]);
            CP_ASYNC16(da, A + (size_t)(bm + row) * K + kof + c4);
            if (bn + row < N) {
                uint32_t db = smem_u32(&Bs[s][row * STR + c4]);
                CP_ASYNC16(db, Bm + (size_t)(bn + row) * K + kof + c4);
            }
        }
    };

    issue(0, 0); CP_COMMIT();
    issue(1, 1); CP_COMMIT();

    for (int kt = 0; kt < nk; kt++) {
        CP_WAIT1();
        __syncthreads();

        if (kt + 2 < nk) issue((kt + 2) % STAGES, kt + 2);
        CP_COMMIT();

        int s = kt % STAGES;
        const uint32_t* sa = &As[s][0];
        const uint32_t* sb = &Bs[s][0];

        #pragma unroll
        for (int ks = 0; ks < 4; ks++) {
            uint32_t af[4][4], bf[4][2];
            #pragma unroll
            for (int mt = 0; mt < 4; mt++) {
                int m = wm * 64 + mt * 16;
                af[mt][0] = sa[(m + gid)     * STR + ks * 8 + tig];
                af[mt][1] = sa[(m + gid + 8) * STR + ks * 8 + tig];
                af[mt][2] = sa[(m + gid)     * STR + ks * 8 + tig + 4];
                af[mt][3] = sa[(m + gid + 8) * STR + ks * 8 + tig + 4];
            }
            #pragma unroll
            for (int nt = 0; nt < 4; nt++) {
                int n = wn * 32 + nt * 8;
                bf[nt][0] = sb[(n + gid) * STR + ks * 8 + tig];
                bf[nt][1] = sb[(n + gid) * STR + ks * 8 + tig + 4];
            }
            if (CVT) {
                #pragma unroll
                for (int mt = 0; mt < 4; mt++)
                    #pragma unroll
                    for (int i = 0; i < 4; i++)
                        af[mt][i] = f2tf32(__uint_as_float(af[mt][i]));
                #pragma unroll
                for (int nt = 0; nt < 4; nt++) {
                    bf[nt][0] = f2tf32(__uint_as_float(bf[nt][0]));
                    bf[nt][1] = f2tf32(__uint_as_float(bf[nt][1]));
                }
            }
            #pragma unroll
            for (int mt = 0; mt < 4; mt++)
                #pragma unroll
                for (int nt = 0; nt < 4; nt++)
                    mma_tf32(acc[mt][nt], af[mt], bf[nt]);
        }
    }

    #pragma unroll
    for (int mt = 0; mt < 4; mt++) {
        #pragma unroll
        for (int nt = 0; nt < 4; nt++) {
            int mrow0 = bm + wm * 64 + mt * 16 + gid;
            int ncol  = bn + wn * 32 + nt * 8 + tig * 2;
            if (ncol < N) {
                float bv0 = bias[ncol], bv1 = bias[ncol + 1];
                float v0 = acc[mt][nt][0] + bv0;
                float v1 = acc[mt][nt][1] + bv1;
                float v2 = acc[mt][nt][2] + bv0;
                float v3 = acc[mt][nt][3] + bv1;
                if (relu) {
                    v0 = v0 > 0.f ? v0 : 0.f;  v1 = v1 > 0.f ? v1 : 0.f;
                    v2 = v2 > 0.f ? v2 : 0.f;  v3 = v3 > 0.f ? v3 : 0.f;
                }
                *(float2*)&C[(size_t)mrow0 * N + ncol]       = make_float2(v0, v1);
                *(float2*)&C[(size_t)(mrow0 + 8) * N + ncol] = make_float2(v2, v3);
            }
        }
    }
}

// dual-operand gx GEMM: blockIdx.z selects (Bq,biasq,Cq) vs (Bk,biask,Ck)
__global__ void __launch_bounds__(256, 2) tf32gemm_dual(
    const float* __restrict__ A,
    const float* __restrict__ Bq, const float* __restrict__ biasq, float* __restrict__ Cq,
    const float* __restrict__ Bk, const float* __restrict__ biask, float* __restrict__ Ck,
    int M, int N, int K)
{
    __shared__ uint32_t As[STAGES][128 * STR];
    __shared__ uint32_t Bs[STAGES][128 * STR];
    const float* Bm   = blockIdx.z ? Bk    : Bq;
    const float* bias = blockIdx.z ? biask : biasq;
    float*       C    = blockIdx.z ? Ck    : Cq;
    gemm_body<0>(A, Bm, bias, C, M, N, K, 0, As, Bs);
}

// merged MLP layer-1: z selects (hqs,W1_q,b1_q,t1q) vs (hks,W1_k,b1_k,t1k); relu
__global__ void __launch_bounds__(256, 2) mlp1_dual(
    const float* __restrict__ Aq, const float* __restrict__ Bq,
    const float* __restrict__ biasq, float* __restrict__ Cq,
    const float* __restrict__ Ak, const float* __restrict__ Bk,
    const float* __restrict__ biask, float* __restrict__ Ck)
{
    __shared__ uint32_t As[STAGES][128 * STR];
    __shared__ uint32_t Bs[STAGES][128 * STR];
    const float* A    = blockIdx.z ? Ak    : Aq;
    const float* Bm   = blockIdx.z ? Bk    : Bq;
    const float* bias = blockIdx.z ? biask : biasq;
    float*       C    = blockIdx.z ? Ck    : Cq;
    gemm_body<1>(A, Bm, bias, C, MTOT, SOH, SD, 1, As, Bs);
}

// merged MLP layer-2: z=0 -> out_q (N=SQD, 8 x-tiles), z=1 -> out_k (N=SKD, 2 x-tiles)
__global__ void __launch_bounds__(256, 2) mlp2_dual(
    const float* __restrict__ Aq, const float* __restrict__ Bq,
    const float* __restrict__ biasq, float* __restrict__ Cq,
    const float* __restrict__ Ak, const float* __restrict__ Bk,
    const float* __restrict__ biask, float* __restrict__ Ck)
{
    if (blockIdx.z == 1 && blockIdx.x >= SKD / 128) return;
    __shared__ uint32_t As[STAGES][128 * STR];
    __shared__ uint32_t Bs[STAGES][128 * STR];
    const float* A    = blockIdx.z ? Ak    : Aq;
    const float* Bm   = blockIdx.z ? Bk    : Bq;
    const float* bias = blockIdx.z ? biask : biasq;
    float*       C    = blockIdx.z ? Ck    : Cq;
    int N             = blockIdx.z ? SKD   : SQD;
    gemm_body<1>(A, Bm, bias, C, MTOT, N, SOH, 0, As, Bs);
}

// ---------------- persistent LSTM recurrence ---------------------------------
__device__ __forceinline__ float sigf(float x) { return 1.f / (1.f + expf(-x)); }

template<int N>
__device__ __forceinline__ void reduce_stage(float* acc, int lane, int ofs)
{
    bool hi = (lane & ofs) != 0;
    #pragma unroll
    for (int i = 0; i < N; i++) {
        float send = hi ? acc[i] : acc[i + N];
        float recv = __shfl_xor_sync(0xffffffffu, send, ofs);
        float keep = hi ? acc[i + N] : acc[i];
        acc[i] = keep + recv;
    }
}

#define KCACHE 512

__global__ void __launch_bounds__(256, 2) lstm_persistent(
    const float* __restrict__ hq0, const float* __restrict__ cq0,
    const float* __restrict__ hk0, const float* __restrict__ ck0,
    const float* __restrict__ Wh_q, const float* __restrict__ bh_q,
    const float* __restrict__ Wh_k, const float* __restrict__ bh_k,
    float* __restrict__ out)
{
    __shared__ __align__(16) float hs[SB][SD + 4];
    __shared__ __align__(16) float Wc[32 * KCACHE];

    int cta  = blockIdx.x;
    int lstm = cta >> 7;
    int ublk = (cta & 127) * 8;

    const float* Wh  = lstm ? Wh_k : Wh_q;
    const float* bh  = lstm ? bh_k : bh_q;
    const float* gx  = lstm ? g_gxk : g_gxq;
    float*       hss = lstm ? g_hks : g_hqs;
    const float* h0  = lstm ? hk0 : hq0;
    const float* c0  = lstm ? ck0 : cq0;
    Bar* bar = &g_bar[lstm];
    const int nblk = 128;

    int tid = threadIdx.x;
    int w = tid >> 5, lane = tid & 31;
    int u = ublk + w;
    int gate = lane >> 3, b = lane & 7;
    int r = gate * SD + u;
    float bhr = bh[r];

    for (int idx = tid; idx < 32 * (KCACHE / 4); idx += 256) {
        int cr = idx >> 7;
        int f4 = idx & 127;
        int ww = cr >> 2, gg = cr & 3;
        const float4* src = (const float4*)(Wh + ((size_t)(gg * SD + ublk + ww)) * SD) + f4;
        *(float4*)&Wc[cr * KCACHE + f4 * 4] = *src;
    }

    const float* wbase0 = Wh + ((size_t)(0 * SD + u)) * SD + lane * 4;
    const float* wbase1 = Wh + ((size_t)(1 * SD + u)) * SD + lane * 4;
    const float* wbase2 = Wh + ((size_t)(2 * SD + u)) * SD + lane * 4;
    const float* wbase3 = Wh + ((size_t)(3 * SD + u)) * SD + lane * 4;

    float creg = 0.f, hlast = 0.f;
    if (lane < 8) creg = c0[b * SD + u];

    int sense = 0;
    unsigned mask = 0xffffffffu;

    const float* gxp = gx + (size_t)b * SS * SG + r;
    float gxv = __ldcg(gxp);   // t = 0

    __syncthreads();

    for (int t = 0; t < SS; t++) {
        const float* hin = (t == 0) ? h0 : g_h[lstm][t & 1];

        // stage h via cp.async (no register round-trip in the serial chain)
        for (int i4 = tid; i4 < SB * SD / 4; i4 += 256) {
            int bb = i4 >> 8, d4 = (i4 & 255) * 4;
            CP_ASYNC16(smem_u32(&hs[bb][d4]), hin + (size_t)i4 * 4);
        }
        CP_COMMIT();
        CP_WAIT0();
        __syncthreads();

        ull acc2[32];
        #pragma unroll
        for (int i = 0; i < 32; i++) acc2[i] = 0ull;

        #pragma unroll
        for (int it = 0; it < 8; it++) {
            ulonglong2 wv0, wv1, wv2, wv3;
            if (it < KCACHE / 128) {
                int ko = it * 128 + lane * 4;
                wv0 = *(const ulonglong2*)&Wc[(w * 4 + 0) * KCACHE + ko];
                wv1 = *(const ulonglong2*)&Wc[(w * 4 + 1) * KCACHE + ko];
                wv2 = *(const ulonglong2*)&Wc[(w * 4 + 2) * KCACHE + ko];
                wv3 = *(const ulonglong2*)&Wc[(w * 4 + 3) * KCACHE + ko];
            } else {
                wv0 = *(const ulonglong2*)(wbase0 + it * 128);
                wv1 = *(const ulonglong2*)(wbase1 + it * 128);
                wv2 = *(const ulonglong2*)(wbase2 + it * 128);
                wv3 = *(const ulonglong2*)(wbase3 + it * 128);
            }

            #pragma unroll
            for (int bb = 0; bb < 8; bb++) {
                ulonglong2 hp = *(const ulonglong2*)&hs[bb][it * 128 + lane * 4];
                ffma2(acc2[0 * 8 + bb], wv0.x, hp.x);
                ffma2(acc2[0 * 8 + bb], wv0.y, hp.y);
                ffma2(acc2[1 * 8 + bb], wv1.x, hp.x);
                ffma2(acc2[1 * 8 + bb], wv1.y, hp.y);
                ffma2(acc2[2 * 8 + bb], wv2.x, hp.x);
                ffma2(acc2[2 * 8 + bb], wv2.y, hp.y);
                ffma2(acc2[3 * 8 + bb], wv3.x, hp.x);
                ffma2(acc2[3 * 8 + bb], wv3.y, hp.y);
            }
        }

        float gxv_cur = gxv;
        if (t + 1 < SS) gxv = __ldcg(gxp + (size_t)(t + 1) * SG);  // prefetch t+1

        float acc[32];
        #pragma unroll
        for (int i = 0; i < 32; i++) acc[i] = lo32f(acc2[i]) + hi32f(acc2[i]);

        reduce_stage<16>(acc, lane, 16);
        reduce_stage<8>(acc, lane, 8);
        reduce_stage<4>(acc, lane, 4);
        reduce_stage<2>(acc, lane, 2);
        reduce_stage<1>(acc, lane, 1);

        float a = acc[0] + gxv_cur + bhr;

        float gi = __shfl_sync(mask, a, b);
        float gf = __shfl_sync(mask, a, 8 + b);
        float gg = __shfl_sync(mask, a, 16 + b);
        float go = __shfl_sync(mask, a, 24 + b);

        if (lane < 8) {
            float cn = sigf(gf) * creg + sigf(gi) * tanhf(gg);
            float hn = sigf(go) * tanhf(cn);
            creg = cn;
            hlast = hn;
            g_h[lstm][(t & 1) ^ 1][b * SD + u] = hn;
            hss[((size_t)b * SS + t) * SD + u] = hn;
        }

        // per-LSTM grid barrier (sense-reversing)
        __syncthreads();
        if (tid == 0) {
            sense ^= 1;
            __threadfence();
            if (atomicAdd((int*)&bar->count, 1) == nblk - 1) {
                bar->count = 0;
                __threadfence();
                bar->sense = sense;
            } else {
                while (bar->sense != sense) { }
            }
            __threadfence();
        }
        __syncthreads();
    }

    if (lane < 8) {
        const size_t base = (size_t)MTOT * SQD + (size_t)MTOT * SKD;
        out[base + (size_t)lstm * 2 * SB * SD + b * SD + u] = hlast;
        out[base + (size_t)lstm * 2 * SB * SD + SB * SD + b * SD + u] = creg;
    }
}

// ---------------- barrier init -----------------------------------------------
__global__ void init_barrier()
{
    if (threadIdx.x == 0 && blockIdx.x == 0) {
        g_bar[0].count = 0; g_bar[0].sense = 0;
        g_bar[1].count = 0; g_bar[1].sense = 0;
    }
}

// ---------------- launch ------------------------------------------------------
// Launch order (ncu -s 5 -c 1 lands on OUR idx-3 launch):
//   0 init_barrier, 1 round_all, 2 tf32gemm_dual, 3 lstm_persistent <- captured,
//   4 mlp1_dual, 5 mlp2_dual
extern "C" void kernel_launch(void* const* d_in, const int* in_sizes, int n_in,
                              void* d_out, int out_size)
{
    const float* x    = (const float*)d_in[0];
    const float* hq   = (const float*)d_in[1];
    const float* cq   = (const float*)d_in[2];
    const float* hk   = (const float*)d_in[3];
    const float* ck   = (const float*)d_in[4];
    const float* Wi_q = (const float*)d_in[5];
    const float* Wh_q = (const float*)d_in[6];
    const float* bi_q = (const float*)d_in[7];
    const float* bh_q = (const float*)d_in[8];
    const float* Wi_k = (const float*)d_in[9];
    const float* Wh_k = (const float*)d_in[10];
    const float* bi_k = (const float*)d_in[11];
    const float* bh_k = (const float*)d_in[12];
    const float* W1_q = (const float*)d_in[13];
    const float* b1_q = (const float*)d_in[14];
    const float* W2_q = (const float*)d_in[15];
    const float* b2_q = (const float*)d_in[16];
    const float* W1_k = (const float*)d_in[17];
    const float* b1_k = (const float*)d_in[18];
    const float* W2_k = (const float*)d_in[19];
    const float* b2_k = (const float*)d_in[20];
    float* out = (float*)d_out;

    float *gxq, *gxk, *hqs, *hks, *t1q, *t1k, *xr, *wq, *wk;
    cudaGetSymbolAddress((void**)&gxq, g_gxq);
    cudaGetSymbolAddress((void**)&gxk, g_gxk);
    cudaGetSymbolAddress((void**)&hqs, g_hqs);
    cudaGetSymbolAddress((void**)&hks, g_hks);
    cudaGetSymbolAddress((void**)&t1q, g_t1q);
    cudaGetSymbolAddress((void**)&t1k, g_t1k);
    cudaGetSymbolAddress((void**)&xr, g_xr);
    cudaGetSymbolAddress((void**)&wq, g_wq);
    cudaGetSymbolAddress((void**)&wk, g_wk);

    int nround = N4X + 2 * N4W;

    init_barrier<<<1, 32>>>();                                        // idx 0
    round_all_k<<<(nround + 255) / 256, 256>>>(                       // idx 1
        (const float4*)x, (float4*)xr,
        (const float4*)Wi_q, (float4*)wq,
        (const float4*)Wi_k, (float4*)wk);

    dim3 ggx(SG / 128, MTOT / 128, 2);
    tf32gemm_dual<<<ggx, 256>>>(xr, wq, bi_q, gxq, wk, bi_k, gxk,     // idx 2
                                MTOT, SG, SD);

    lstm_persistent<<<256, 256>>>(hq, cq, hk, ck,                     // idx 3 (captured)
                                  Wh_q, bh_q, Wh_k, bh_k, out);

    mlp1_dual<<<dim3(1, MTOT / 128, 2), 256>>>(                       // idx 4
        hqs, W1_q, b1_q, t1q, hks, W1_k, b1_k, t1k);
    mlp2_dual<<<dim3(SQD / 128, MTOT / 128, 2), 256>>>(               // idx 5
        t1q, W2_q, b2_q, out, t1k, W2_k, b2_k, out + (size_t)MTOT * SQD);
}

// round 17
// speedup vs baseline: 1.0932x; 1.0932x over previous
#include <cuda_runtime.h>
#include <math.h>
#include <stdint.h>

// Problem dims
#define SB 8
#define SS 2048
#define SD 1024
#define SG 4096          // 4*D
#define SQD 1024
#define SKD 256
#define SOH 64
#define MTOT (SB*SS)     // 16384

typedef unsigned long long ull;

// ---------------- scratch (static device globals; no allocation) -------------
__device__ float g_gxq[(size_t)MTOT * SG];
__device__ float g_gxk[(size_t)MTOT * SG];
__device__ float g_hqs[(size_t)MTOT * SD];
__device__ float g_hks[(size_t)MTOT * SD];
__device__ float g_t1q[(size_t)MTOT * SOH];
__device__ float g_t1k[(size_t)MTOT * SOH];
__device__ float g_xr[(size_t)MTOT * SD];    // tf32-rounded x
__device__ float g_wq[(size_t)SG * SD];      // tf32-rounded Wi_q
__device__ float g_wk[(size_t)SG * SD];      // tf32-rounded Wi_k
__device__ float g_h[2][2][SB * SD];

// per-LSTM barrier, each field on its own 128B line
struct __align__(128) Bar { volatile int count; int p0[31]; volatile int sense; int p1[31]; };
__device__ Bar g_bar[2];

// ---------------- helpers -----------------------------------------------------
__device__ __forceinline__ uint32_t f2tf32(float x)
{
    uint32_t u;
    asm("cvt.rna.tf32.f32 %0, %1;" : "=r"(u) : "f"(x));
    return u;
}

__device__ __forceinline__ void mma_tf32(float* d, const uint32_t* a, const uint32_t* b)
{
    asm volatile(
        "mma.sync.aligned.m16n8k8.row.col.f32.tf32.tf32.f32 "
        "{%0,%1,%2,%3}, {%4,%5,%6,%7}, {%8,%9}, {%0,%1,%2,%3};"
        : "+f"(d[0]), "+f"(d[1]), "+f"(d[2]), "+f"(d[3])
        : "r"(a[0]), "r"(a[1]), "r"(a[2]), "r"(a[3]), "r"(b[0]), "r"(b[1]));
}

__device__ __forceinline__ void ffma2(ull& d, ull a, ull b)
{
    asm("fma.rn.f32x2 %0, %1, %2, %0;" : "+l"(d) : "l"(a), "l"(b));
}

__device__ __forceinline__ float lo32f(ull v) { return __uint_as_float((unsigned)v); }
__device__ __forceinline__ float hi32f(ull v) { return __uint_as_float((unsigned)(v >> 32)); }

__device__ __forceinline__ uint32_t smem_u32(const void* p)
{
    return (uint32_t)__cvta_generic_to_shared(p);
}

#define CP_ASYNC16(dst, src) \
    asm volatile("cp.async.cg.shared.global [%0], [%1], 16;" :: "r"(dst), "l"(src))
#define CP_COMMIT() asm volatile("cp.async.commit_group;")
#define CP_WAIT1()  asm volatile("cp.async.wait_group 1;")

// ---------------- fused elementwise tf32 rounding (x, Wi_q, Wi_k) ------------
#define N4X (MTOT * SD / 4)
#define N4W (SG * SD / 4)

__global__ void round_all_k(const float4* __restrict__ x, float4* __restrict__ xr,
                            const float4* __restrict__ wqi, float4* __restrict__ wqo,
                            const float4* __restrict__ wki, float4* __restrict__ wko)
{
    int i = blockIdx.x * blockDim.x + threadIdx.x;
    const float4* in;
    float4* out;
    int idx;
    if (i < N4X)                { in = x;   out = xr;  idx = i; }
    else if (i < N4X + N4W)     { in = wqi; out = wqo; idx = i - N4X; }
    else if (i < N4X + 2 * N4W) { in = wki; out = wko; idx = i - N4X - N4W; }
    else return;
    float4 v = in[idx];
    v.x = __uint_as_float(f2tf32(v.x));
    v.y = __uint_as_float(f2tf32(v.y));
    v.z = __uint_as_float(f2tf32(v.z));
    v.w = __uint_as_float(f2tf32(v.w));
    out[idx] = v;
}

// ---------------- pipelined tf32 GEMM core -----------------------------------
#define STAGES 3
#define GBK 32
#define STR 36

template<int CVT>
__device__ __forceinline__ void gemm_body(
    const float* __restrict__ A, const float* __restrict__ Bm,
    const float* __restrict__ bias, float* __restrict__ C,
    int M, int N, int K, int relu, int bxtile,
    uint32_t (*As)[128 * STR], uint32_t (*Bs)[128 * STR])
{
    int tid = threadIdx.x, wid = tid >> 5, lane = tid & 31;
    int wm = wid & 1, wn = wid >> 1;
    int bm = blockIdx.y * 128, bn = bxtile * 128;
    int gid = lane >> 2, tig = lane & 3;

    int r0 = tid >> 3;
    int c4 = (tid & 7) * 4;

    float acc[4][4][4];
    #pragma unroll
    for (int mt = 0; mt < 4; mt++)
        #pragma unroll
        for (int nt = 0; nt < 4; nt++)
            #pragma unroll
            for (int i = 0; i < 4; i++) acc[mt][nt][i] = 0.f;

    int nk = K / GBK;

    auto issue = [&](int s, int kt) {
        int kof = kt * GBK;
        #pragma unroll
        for (int j = 0; j < 4; j++) {
            int row = r0 + 32 * j;
            uint32_t da = smem_u32(&As[s][row * STR + c4]);
            CP_ASYNC16(da, A + (size_t)(bm + row) * K + kof + c4);
            if (bn + row < N) {
                uint32_t db = smem_u32(&Bs[s][row * STR + c4]);
                CP_ASYNC16(db, Bm + (size_t)(bn + row) * K + kof + c4);
            }
        }
    };

    issue(0, 0); CP_COMMIT();
    issue(1, 1); CP_COMMIT();

    for (int kt = 0; kt < nk; kt++) {
        CP_WAIT1();
        __syncthreads();

        if (kt + 2 < nk) issue((kt + 2) % STAGES, kt + 2);
        CP_COMMIT();

        int s = kt % STAGES;
        const uint32_t* sa = &As[s][0];
        const uint32_t* sb = &Bs[s][0];

        #pragma unroll
        for (int ks = 0; ks < 4; ks++) {
            uint32_t af[4][4], bf[4][2];
            #pragma unroll
            for (int mt = 0; mt < 4; mt++) {
                int m = wm * 64 + mt * 16;
                af[mt][0] = sa[(m + gid)     * STR + ks * 8 + tig];
                af[mt][1] = sa[(m + gid + 8) * STR + ks * 8 + tig];
                af[mt][2] = sa[(m + gid)     * STR + ks * 8 + tig + 4];
                af[mt][3] = sa[(m + gid + 8) * STR + ks * 8 + tig + 4];
            }
            #pragma unroll
            for (int nt = 0; nt < 4; nt++) {
                int n = wn * 32 + nt * 8;
                bf[nt][0] = sb[(n + gid) * STR + ks * 8 + tig];
                bf[nt][1] = sb[(n + gid) * STR + ks * 8 + tig + 4];
            }
            if (CVT) {
                #pragma unroll
                for (int mt = 0; mt < 4; mt++)
                    #pragma unroll
                    for (int i = 0; i < 4; i++)
                        af[mt][i] = f2tf32(__uint_as_float(af[mt][i]));
                #pragma unroll
                for (int nt = 0; nt < 4; nt++) {
                    bf[nt][0] = f2tf32(__uint_as_float(bf[nt][0]));
                    bf[nt][1] = f2tf32(__uint_as_float(bf[nt][1]));
                }
            }
            #pragma unroll
            for (int mt = 0; mt < 4; mt++)
                #pragma unroll
                for (int nt = 0; nt < 4; nt++)
                    mma_tf32(acc[mt][nt], af[mt], bf[nt]);
        }
    }

    #pragma unroll
    for (int mt = 0; mt < 4; mt++) {
        #pragma unroll
        for (int nt = 0; nt < 4; nt++) {
            int mrow0 = bm + wm * 64 + mt * 16 + gid;
            int ncol  = bn + wn * 32 + nt * 8 + tig * 2;
            if (ncol < N) {
                float bv0 = bias[ncol], bv1 = bias[ncol + 1];
                float v0 = acc[mt][nt][0] + bv0;
                float v1 = acc[mt][nt][1] + bv1;
                float v2 = acc[mt][nt][2] + bv0;
                float v3 = acc[mt][nt][3] + bv1;
                if (relu) {
                    v0 = v0 > 0.f ? v0 : 0.f;  v1 = v1 > 0.f ? v1 : 0.f;
                    v2 = v2 > 0.f ? v2 : 0.f;  v3 = v3 > 0.f ? v3 : 0.f;
                }
                *(float2*)&C[(size_t)mrow0 * N + ncol]       = make_float2(v0, v1);
                *(float2*)&C[(size_t)(mrow0 + 8) * N + ncol] = make_float2(v2, v3);
            }
        }
    }
}

// dual-operand gx GEMM: blockIdx.z selects (Bq,biasq,Cq) vs (Bk,biask,Ck)
__global__ void __launch_bounds__(256, 2) tf32gemm_dual(
    const float* __restrict__ A,
    const float* __restrict__ Bq, const float* __restrict__ biasq, float* __restrict__ Cq,
    const float* __restrict__ Bk, const float* __restrict__ biask, float* __restrict__ Ck,
    int M, int N, int K)
{
    __shared__ uint32_t As[STAGES][128 * STR];
    __shared__ uint32_t Bs[STAGES][128 * STR];
    const float* Bm   = blockIdx.z ? Bk    : Bq;
    const float* bias = blockIdx.z ? biask : biasq;
    float*       C    = blockIdx.z ? Ck    : Cq;
    gemm_body<0>(A, Bm, bias, C, M, N, K, 0, blockIdx.x, As, Bs);
}

// merged MLP layer-1 (relu): z selects q/k operand set
__global__ void __launch_bounds__(256, 2) mlp1_dual(
    const float* __restrict__ Aq, const float* __restrict__ Bq,
    const float* __restrict__ biasq, float* __restrict__ Cq,
    const float* __restrict__ Ak, const float* __restrict__ Bk,
    const float* __restrict__ biask, float* __restrict__ Ck)
{
    __shared__ uint32_t As[STAGES][128 * STR];
    __shared__ uint32_t Bs[STAGES][128 * STR];
    const float* A    = blockIdx.z ? Ak    : Aq;
    const float* Bm   = blockIdx.z ? Bk    : Bq;
    const float* bias = blockIdx.z ? biask : biasq;
    float*       C    = blockIdx.z ? Ck    : Cq;
    gemm_body<1>(A, Bm, bias, C, MTOT, SOH, SD, 1, 0, As, Bs);
}

// merged MLP layer-2, flattened x: x<8 -> out_q tile x; x>=8 -> out_k tile x-8
__global__ void __launch_bounds__(256, 2) mlp2_merged(
    const float* __restrict__ Aq, const float* __restrict__ Bq,
    const float* __restrict__ biasq, float* __restrict__ Cq,
    const float* __restrict__ Ak, const float* __restrict__ Bk,
    const float* __restrict__ biask, float* __restrict__ Ck)
{
    __shared__ uint32_t As[STAGES][128 * STR];
    __shared__ uint32_t Bs[STAGES][128 * STR];
    int isk = blockIdx.x >= SQD / 128;
    const float* A    = isk ? Ak    : Aq;
    const float* Bm   = isk ? Bk    : Bq;
    const float* bias = isk ? biask : biasq;
    float*       C    = isk ? Ck    : Cq;
    int N             = isk ? SKD   : SQD;
    int bx            = isk ? (blockIdx.x - SQD / 128) : blockIdx.x;
    gemm_body<1>(A, Bm, bias, C, MTOT, N, SOH, 0, bx, As, Bs);
}

// ---------------- persistent LSTM recurrence (exact R15) ---------------------
__device__ __forceinline__ float sigf(float x) { return 1.f / (1.f + expf(-x)); }

template<int N>
__device__ __forceinline__ void reduce_stage(float* acc, int lane, int ofs)
{
    bool hi = (lane & ofs) != 0;
    #pragma unroll
    for (int i = 0; i < N; i++) {
        float send = hi ? acc[i] : acc[i + N];
        float recv = __shfl_xor_sync(0xffffffffu, send, ofs);
        float keep = hi ? acc[i + N] : acc[i];
        acc[i] = keep + recv;
    }
}

#define KCACHE 512

__global__ void __launch_bounds__(256, 2) lstm_persistent(
    const float* __restrict__ hq0, const float* __restrict__ cq0,
    const float* __restrict__ hk0, const float* __restrict__ ck0,
    const float* __restrict__ Wh_q, const float* __restrict__ bh_q,
    const float* __restrict__ Wh_k, const float* __restrict__ bh_k,
    float* __restrict__ out)
{
    __shared__ __align__(16) float hs[SB][SD + 4];
    __shared__ __align__(16) float Wc[32 * KCACHE];

    int cta  = blockIdx.x;
    int lstm = cta >> 7;
    int ublk = (cta & 127) * 8;

    const float* Wh  = lstm ? Wh_k : Wh_q;
    const float* bh  = lstm ? bh_k : bh_q;
    const float* gx  = lstm ? g_gxk : g_gxq;
    float*       hss = lstm ? g_hks : g_hqs;
    const float* h0  = lstm ? hk0 : hq0;
    const float* c0  = lstm ? ck0 : cq0;
    Bar* bar = &g_bar[lstm];
    const int nblk = 128;

    int tid = threadIdx.x;
    int w = tid >> 5, lane = tid & 31;
    int u = ublk + w;
    int gate = lane >> 3, b = lane & 7;
    int r = gate * SD + u;
    float bhr = bh[r];

    for (int idx = tid; idx < 32 * (KCACHE / 4); idx += 256) {
        int cr = idx >> 7;
        int f4 = idx & 127;
        int ww = cr >> 2, gg = cr & 3;
        const float4* src = (const float4*)(Wh + ((size_t)(gg * SD + ublk + ww)) * SD) + f4;
        *(float4*)&Wc[cr * KCACHE + f4 * 4] = *src;
    }

    const float* wbase0 = Wh + ((size_t)(0 * SD + u)) * SD + lane * 4;
    const float* wbase1 = Wh + ((size_t)(1 * SD + u)) * SD + lane * 4;
    const float* wbase2 = Wh + ((size_t)(2 * SD + u)) * SD + lane * 4;
    const float* wbase3 = Wh + ((size_t)(3 * SD + u)) * SD + lane * 4;

    float creg = 0.f, hlast = 0.f;
    if (lane < 8) creg = c0[b * SD + u];

    int sense = 0;
    unsigned mask = 0xffffffffu;

    const float* gxp = gx + (size_t)b * SS * SG + r;
    float gxv = __ldcg(gxp);   // t = 0

    __syncthreads();

    for (int t = 0; t < SS; t++) {
        const float* hin = (t == 0) ? h0 : g_h[lstm][t & 1];

        for (int i = tid * 4; i < SB * SD; i += 1024) {
            float4 v = __ldcg((const float4*)(hin + i));
            *(float4*)&hs[i >> 10][i & 1023] = v;
        }
        __syncthreads();

        ull acc2[32];
        #pragma unroll
        for (int i = 0; i < 32; i++) acc2[i] = 0ull;

        #pragma unroll
        for (int it = 0; it < 8; it++) {
            ulonglong2 wv0, wv1, wv2, wv3;
            if (it < KCACHE / 128) {
                int ko = it * 128 + lane * 4;
                wv0 = *(const ulonglong2*)&Wc[(w * 4 + 0) * KCACHE + ko];
                wv1 = *(const ulonglong2*)&Wc[(w * 4 + 1) * KCACHE + ko];
                wv2 = *(const ulonglong2*)&Wc[(w * 4 + 2) * KCACHE + ko];
                wv3 = *(const ulonglong2*)&Wc[(w * 4 + 3) * KCACHE + ko];
            } else {
                wv0 = *(const ulonglong2*)(wbase0 + it * 128);
                wv1 = *(const ulonglong2*)(wbase1 + it * 128);
                wv2 = *(const ulonglong2*)(wbase2 + it * 128);
                wv3 = *(const ulonglong2*)(wbase3 + it * 128);
            }

            #pragma unroll
            for (int bb = 0; bb < 8; bb++) {
                ulonglong2 hp = *(const ulonglong2*)&hs[bb][it * 128 + lane * 4];
                ffma2(acc2[0 * 8 + bb], wv0.x, hp.x);
                ffma2(acc2[0 * 8 + bb], wv0.y, hp.y);
                ffma2(acc2[1 * 8 + bb], wv1.x, hp.x);
                ffma2(acc2[1 * 8 + bb], wv1.y, hp.y);
                ffma2(acc2[2 * 8 + bb], wv2.x, hp.x);
                ffma2(acc2[2 * 8 + bb], wv2.y, hp.y);
                ffma2(acc2[3 * 8 + bb], wv3.x, hp.x);
                ffma2(acc2[3 * 8 + bb], wv3.y, hp.y);
            }
        }

        float gxv_cur = gxv;
        if (t + 1 < SS) gxv = __ldcg(gxp + (size_t)(t + 1) * SG);  // prefetch t+1

        float acc[32];
        #pragma unroll
        for (int i = 0; i < 32; i++) acc[i] = lo32f(acc2[i]) + hi32f(acc2[i]);

        reduce_stage<16>(acc, lane, 16);
        reduce_stage<8>(acc, lane, 8);
        reduce_stage<4>(acc, lane, 4);
        reduce_stage<2>(acc, lane, 2);
        reduce_stage<1>(acc, lane, 1);

        float a = acc[0] + gxv_cur + bhr;

        float gi = __shfl_sync(mask, a, b);
        float gf = __shfl_sync(mask, a, 8 + b);
        float gg = __shfl_sync(mask, a, 16 + b);
        float go = __shfl_sync(mask, a, 24 + b);

        if (lane < 8) {
            float cn = sigf(gf) * creg + sigf(gi) * tanhf(gg);
            float hn = sigf(go) * tanhf(cn);
            creg = cn;
            hlast = hn;
            g_h[lstm][(t & 1) ^ 1][b * SD + u] = hn;
            hss[((size_t)b * SS + t) * SD + u] = hn;
        }

        // per-LSTM grid barrier (sense-reversing)
        __syncthreads();
        if (tid == 0) {
            sense ^= 1;
            __threadfence();
            if (atomicAdd((int*)&bar->count, 1) == nblk - 1) {
                bar->count = 0;
                __threadfence();
                bar->sense = sense;
            } else {
                while (bar->sense != sense) { }
            }
            __threadfence();
        }
        __syncthreads();
    }

    if (lane < 8) {
        const size_t base = (size_t)MTOT * SQD + (size_t)MTOT * SKD;
        out[base + (size_t)lstm * 2 * SB * SD + b * SD + u] = hlast;
        out[base + (size_t)lstm * 2 * SB * SD + SB * SD + b * SD + u] = creg;
    }
}

// ---------------- barrier init -----------------------------------------------
__global__ void init_barrier()
{
    if (threadIdx.x == 0 && blockIdx.x == 0) {
        g_bar[0].count = 0; g_bar[0].sense = 0;
        g_bar[1].count = 0; g_bar[1].sense = 0;
    }
}

// ---------------- launch ------------------------------------------------------
// Launch order (ncu -s 5 -c 1 lands on OUR idx-3 launch):
//   0 init_barrier, 1 round_all, 2 tf32gemm_dual, 3 lstm_persistent <- captured,
//   4 mlp1_dual, 5 mlp2_merged
extern "C" void kernel_launch(void* const* d_in, const int* in_sizes, int n_in,
                              void* d_out, int out_size)
{
    const float* x    = (const float*)d_in[0];
    const float* hq   = (const float*)d_in[1];
    const float* cq   = (const float*)d_in[2];
    const float* hk   = (const float*)d_in[3];
    const float* ck   = (const float*)d_in[4];
    const float* Wi_q = (const float*)d_in[5];
    const float* Wh_q = (const float*)d_in[6];
    const float* bi_q = (const float*)d_in[7];
    const float* bh_q = (const float*)d_in[8];
    const float* Wi_k = (const float*)d_in[9];
    const float* Wh_k = (const float*)d_in[10];
    const float* bi_k = (const float*)d_in[11];
    const float* bh_k = (const float*)d_in[12];
    const float* W1_q = (const float*)d_in[13];
    const float* b1_q = (const float*)d_in[14];
    const float* W2_q = (const float*)d_in[15];
    const float* b2_q = (const float*)d_in[16];
    const float* W1_k = (const float*)d_in[17];
    const float* b1_k = (const float*)d_in[18];
    const float* W2_k = (const float*)d_in[19];
    const float* b2_k = (const float*)d_in[20];
    float* out = (float*)d_out;

    float *gxq, *gxk, *hqs, *hks, *t1q, *t1k, *xr, *wq, *wk;
    cudaGetSymbolAddress((void**)&gxq, g_gxq);
    cudaGetSymbolAddress((void**)&gxk, g_gxk);
    cudaGetSymbolAddress((void**)&hqs, g_hqs);
    cudaGetSymbolAddress((void**)&hks, g_hks);
    cudaGetSymbolAddress((void**)&t1q, g_t1q);
    cudaGetSymbolAddress((void**)&t1k, g_t1k);
    cudaGetSymbolAddress((void**)&xr, g_xr);
    cudaGetSymbolAddress((void**)&wq, g_wq);
    cudaGetSymbolAddress((void**)&wk, g_wk);

    int nround = N4X + 2 * N4W;

    init_barrier<<<1, 32>>>();                                        // idx 0
    round_all_k<<<(nround + 255) / 256, 256>>>(                       // idx 1
        (const float4*)x, (float4*)xr,
        (const float4*)Wi_q, (float4*)wq,
        (const float4*)Wi_k, (float4*)wk);

    dim3 ggx(SG / 128, MTOT / 128, 2);
    tf32gemm_dual<<<ggx, 256>>>(xr, wq, bi_q, gxq, wk, bi_k, gxk,     // idx 2
                                MTOT, SG, SD);

    lstm_persistent<<<256, 256>>>(hq, cq, hk, ck,                     // idx 3 (captured)
                                  Wh_q, bh_q, Wh_k, bh_k, out);

    mlp1_dual<<<dim3(1, MTOT / 128, 2), 256>>>(                       // idx 4
        hqs, W1_q, b1_q, t1q, hks, W1_k, b1_k, t1k);
    mlp2_merged<<<dim3((SQD + SKD) / 128, MTOT / 128), 256>>>(        // idx 5
        t1q, W2_q, b2_q, out, t1k, W2_k, b2_k, out + (size_t)MTOT * SQD);
}